// round 3
// baseline (speedup 1.0000x reference)
#include <cuda_runtime.h>
#include <math.h>

#define D_DIM 512
#define MAX_N 65536
#define MAX_C 1024

// Scratch (allocation-free rule: __device__ globals).
// NOTE: these symbols are ONLY referenced from device code. Passing them as
// kernel arguments from host code is UB (host shadow address) — that was the
// round-0..2 bug.
__device__ float g_inv[MAX_N];               // 1/max(||feat_row||, eps)
__device__ float g_sums[MAX_C * D_DIM];      // segment sums of normalized feats
__device__ float g_cnt[MAX_C];               // per-class counts
__device__ float g_protos[MAX_C * D_DIM];    // updated prototype bank
__device__ int   g_lab64;                    // 1 if labels are int64, else int32

// ---------------------------------------------------------------------------
// Detect label dtype: for int64 labels < 2^31 (little-endian), every odd
// 32-bit word is 0. For int32 random labels in [0,1024) the odds that 128
// consecutive odd-index words are all 0 are ~(1/1024)^128 ~ 0.
// Deterministic, graph-capturable.
// ---------------------------------------------------------------------------
__global__ void detect_labels(const int* __restrict__ words, int n_words) {
    int all_zero = 1;
    for (int i = 1; i < 256 && i < n_words; i += 2)
        if (words[i] != 0) { all_zero = 0; break; }
    g_lab64 = all_zero;
}

// ---------------------------------------------------------------------------
// Zero the accumulators (must run every launch: graph gets replayed)
// ---------------------------------------------------------------------------
__global__ void zero_kernel() {
    int i = blockIdx.x * blockDim.x + threadIdx.x;
    if (i < MAX_C * D_DIM) g_sums[i] = 0.0f;
    if (i < MAX_C)         g_cnt[i]  = 0.0f;
}

// ---------------------------------------------------------------------------
// Per-row L2 norm + atomic segment scatter of the normalized row.
// One block (128 threads) per row; each thread owns one float4 (D=512).
// ---------------------------------------------------------------------------
__global__ void __launch_bounds__(128) normalize_scatter(
    const float* __restrict__ feats,
    const void* __restrict__ labels,
    int Ccls)
{
    const int row = blockIdx.x;
    const int t   = threadIdx.x;  // 0..127

    const float4 v = reinterpret_cast<const float4*>(feats + (size_t)row * D_DIM)[t];
    float ss = v.x * v.x + v.y * v.y + v.z * v.z + v.w * v.w;

    #pragma unroll
    for (int o = 16; o > 0; o >>= 1) ss += __shfl_xor_sync(0xffffffffu, ss, o);

    __shared__ float warp_ss[4];
    if ((t & 31) == 0) warp_ss[t >> 5] = ss;
    __syncthreads();
    const float tot = warp_ss[0] + warp_ss[1] + warp_ss[2] + warp_ss[3];
    const float inv = 1.0f / fmaxf(sqrtf(tot), 1e-12f);

    if (t == 0) g_inv[row] = inv;

    int lab;
    if (g_lab64) lab = (int)reinterpret_cast<const long long*>(labels)[row];
    else         lab = reinterpret_cast<const int*>(labels)[row];
    if (lab < 0) lab = 0;
    if (lab >= Ccls) lab = Ccls - 1;

    float* s = g_sums + (size_t)lab * D_DIM + t * 4;
    atomicAdd(s + 0, v.x * inv);
    atomicAdd(s + 1, v.y * inv);
    atomicAdd(s + 2, v.z * inv);
    atomicAdd(s + 3, v.w * inv);
    if (t == 0) atomicAdd(&g_cnt[lab], 1.0f);
}

// ---------------------------------------------------------------------------
// Prototype update: ema = l2norm(0.9*p + 0.1*mean); keep old p if count==0.
// One block (128 threads) per class.
// ---------------------------------------------------------------------------
__global__ void __launch_bounds__(128) proto_update(
    const float* __restrict__ protos)
{
    const int c = blockIdx.x;
    const int t = threadIdx.x;

    const float cnt   = g_cnt[c];
    const float denom = fmaxf(cnt, 1.0f);

    const float4 p = reinterpret_cast<const float4*>(protos + (size_t)c * D_DIM)[t];
    const float4 s = reinterpret_cast<const float4*>(g_sums  + (size_t)c * D_DIM)[t];

    const float momentum = 0.9f;
    const float one_m    = 1.0f - momentum;
    float4 m;
    m.x = momentum * p.x + one_m * (s.x / denom);
    m.y = momentum * p.y + one_m * (s.y / denom);
    m.z = momentum * p.z + one_m * (s.z / denom);
    m.w = momentum * p.w + one_m * (s.w / denom);

    float ss = m.x * m.x + m.y * m.y + m.z * m.z + m.w * m.w;
    #pragma unroll
    for (int o = 16; o > 0; o >>= 1) ss += __shfl_xor_sync(0xffffffffu, ss, o);
    __shared__ float warp_ss[4];
    if ((t & 31) == 0) warp_ss[t >> 5] = ss;
    __syncthreads();
    const float tot = warp_ss[0] + warp_ss[1] + warp_ss[2] + warp_ss[3];
    const float inv = 1.0f / fmaxf(sqrtf(tot), 1e-12f);

    float4 o4;
    if (cnt > 0.0f) {
        o4.x = m.x * inv; o4.y = m.y * inv; o4.z = m.z * inv; o4.w = m.w * inv;
    } else {
        o4 = p;
    }
    reinterpret_cast<float4*>(g_protos + (size_t)c * D_DIM)[t] = o4;
}

// ---------------------------------------------------------------------------
// SGEMM: sim[N, C] = (feats * g_inv[row]) @ g_protos^T
// 128x128x16 tiles, 256 threads, 8x8 per-thread micro-tile. A-rows scaled by
// g_inv at shared-fill time (normalized f never materialized).
// g_inv / g_protos referenced as device symbols INSIDE the kernel.
// ---------------------------------------------------------------------------
#define BM 128
#define BN 128
#define BK 16
#define TM 8
#define TN 8

__global__ void __launch_bounds__(256) gemm_kernel(
    const float* __restrict__ A,     // feats [N, D]
    float* __restrict__ Cmat,        // [N, C]
    int N, int Ccls)
{
    __shared__ float As[BK][BM];
    __shared__ float Bs[BK][BN];
    const float* __restrict__ B   = g_protos;   // [C, D]  (device symbol)
    const float* __restrict__ inv = g_inv;      // [N]     (device symbol)

    const int bm  = blockIdx.y * BM;
    const int bn  = blockIdx.x * BN;
    const int tid = threadIdx.x;

    // Load mapping: tile = 128 rows x 16 k-floats = 512 float4; 2 per thread.
    // id -> (row = id>>2, kq = id&3): 4 consecutive threads stream one row's
    // 64 contiguous bytes (fully coalesced LDG.128).
    const int id0   = tid;
    const int id1   = tid + 256;
    const int arow0 = id0 >> 2, akq0 = id0 & 3;
    const int arow1 = id1 >> 2, akq1 = id1 & 3;

    const float sa0 = inv[bm + arow0];
    const float sa1 = inv[bm + arow1];

    const float* Abase0 = A + (size_t)(bm + arow0) * D_DIM;
    const float* Abase1 = A + (size_t)(bm + arow1) * D_DIM;
    const float* Bbase0 = B + (size_t)(bn + arow0) * D_DIM;
    const float* Bbase1 = B + (size_t)(bn + arow1) * D_DIM;

    const int tm = (tid >> 4) * TM;   // 0..120
    const int tn = (tid & 15) * TN;   // 0..120

    float acc[TM][TN];
    #pragma unroll
    for (int i = 0; i < TM; i++)
        #pragma unroll
        for (int j = 0; j < TN; j++) acc[i][j] = 0.0f;

    for (int k0 = 0; k0 < D_DIM; k0 += BK) {
        // ---- fill shared tiles (transposed: [k][m]) ----
        float4 a0 = *reinterpret_cast<const float4*>(Abase0 + k0 + akq0 * 4);
        float4 a1 = *reinterpret_cast<const float4*>(Abase1 + k0 + akq1 * 4);
        float4 b0 = *reinterpret_cast<const float4*>(Bbase0 + k0 + akq0 * 4);
        float4 b1 = *reinterpret_cast<const float4*>(Bbase1 + k0 + akq1 * 4);

        As[akq0 * 4 + 0][arow0] = a0.x * sa0;
        As[akq0 * 4 + 1][arow0] = a0.y * sa0;
        As[akq0 * 4 + 2][arow0] = a0.z * sa0;
        As[akq0 * 4 + 3][arow0] = a0.w * sa0;
        As[akq1 * 4 + 0][arow1] = a1.x * sa1;
        As[akq1 * 4 + 1][arow1] = a1.y * sa1;
        As[akq1 * 4 + 2][arow1] = a1.z * sa1;
        As[akq1 * 4 + 3][arow1] = a1.w * sa1;

        Bs[akq0 * 4 + 0][arow0] = b0.x;
        Bs[akq0 * 4 + 1][arow0] = b0.y;
        Bs[akq0 * 4 + 2][arow0] = b0.z;
        Bs[akq0 * 4 + 3][arow0] = b0.w;
        Bs[akq1 * 4 + 0][arow1] = b1.x;
        Bs[akq1 * 4 + 1][arow1] = b1.y;
        Bs[akq1 * 4 + 2][arow1] = b1.z;
        Bs[akq1 * 4 + 3][arow1] = b1.w;

        __syncthreads();

        // ---- compute ----
        #pragma unroll
        for (int k = 0; k < BK; k++) {
            float ra[TM], rb[TN];
            *reinterpret_cast<float4*>(&ra[0]) = *reinterpret_cast<const float4*>(&As[k][tm]);
            *reinterpret_cast<float4*>(&ra[4]) = *reinterpret_cast<const float4*>(&As[k][tm + 4]);
            *reinterpret_cast<float4*>(&rb[0]) = *reinterpret_cast<const float4*>(&Bs[k][tn]);
            *reinterpret_cast<float4*>(&rb[4]) = *reinterpret_cast<const float4*>(&Bs[k][tn + 4]);
            #pragma unroll
            for (int i = 0; i < TM; i++)
                #pragma unroll
                for (int j = 0; j < TN; j++)
                    acc[i][j] = fmaf(ra[i], rb[j], acc[i][j]);
        }
        __syncthreads();
    }

    // ---- writeback (float4) ----
    #pragma unroll
    for (int i = 0; i < TM; i++) {
        float* out = Cmat + (size_t)(bm + tm + i) * Ccls + bn + tn;
        float4 o0 = make_float4(acc[i][0], acc[i][1], acc[i][2], acc[i][3]);
        float4 o1 = make_float4(acc[i][4], acc[i][5], acc[i][6], acc[i][7]);
        *reinterpret_cast<float4*>(out)     = o0;
        *reinterpret_cast<float4*>(out + 4) = o1;
    }
}

// ---------------------------------------------------------------------------
extern "C" void kernel_launch(void* const* d_in, const int* in_sizes, int n_in,
                              void* d_out, int out_size)
{
    // Identify inputs by element count (robust to metadata ordering):
    //   feats:      N*512 = 33,554,432 (largest)
    //   prototypes: C*512 =    524,288 (middle)
    //   labels:     N     =     65,536 (smallest)
    int i_feats = 0, i_protos = 0, i_labels = 0;
    for (int i = 1; i < n_in; i++) {
        if (in_sizes[i] > in_sizes[i_feats])  i_feats  = i;
        if (in_sizes[i] < in_sizes[i_labels]) i_labels = i;
    }
    for (int i = 0; i < n_in; i++)
        if (i != i_feats && i != i_labels) i_protos = i;

    const float* feats  = (const float*)d_in[i_feats];
    const float* protos = (const float*)d_in[i_protos];
    const void*  labels = d_in[i_labels];

    const int N = in_sizes[i_labels];
    const int C = in_sizes[i_protos] / D_DIM;
    float* out = (float*)d_out;

    // 0. detect label dtype (int32 vs int64), deterministic
    detect_labels<<<1, 1>>>((const int*)labels, N);
    // 1. zero accumulators
    {
        int total = MAX_C * D_DIM;
        zero_kernel<<<(total + 255) / 256, 256>>>();
    }
    // 2. normalize rows + segment scatter
    normalize_scatter<<<N, 128>>>(feats, labels, C);
    // 3. prototype EMA + renorm
    proto_update<<<C, 128>>>(protos);
    // 4. similarity GEMM
    dim3 grid(C / BN, N / BM);
    gemm_kernel<<<grid, 256>>>(feats, out, N, C);
}

// round 5
// speedup vs baseline: 2.5295x; 2.5295x over previous
#include <cuda_runtime.h>
#include <cuda_bf16.h>
#include <math.h>
#include <stdint.h>

#define D_DIM 512
#define MAX_N 65536
#define MAX_C 1024

// Scratch (allocation-free rule). Referenced ONLY from device code.
__device__ float g_inv[MAX_N];
__device__ float g_sums[MAX_C * D_DIM];
__device__ float g_cnt[MAX_C];
__device__ float g_protos[MAX_C * D_DIM];
__device__ int   g_lab64;

// ---------------------------------------------------------------------------
__device__ __forceinline__ uint32_t smem_u32(const void* p) {
    uint32_t a;
    asm("{ .reg .u64 t; cvta.to.shared.u64 t, %1; cvt.u32.u64 %0, t; }"
        : "=r"(a) : "l"(p));
    return a;
}
__device__ __forceinline__ uint32_t sw128(uint32_t off) { return off ^ ((off >> 3) & 0x70); }
__device__ __forceinline__ uint32_t bf2u(__nv_bfloat162 v) {
    return *reinterpret_cast<uint32_t*>(&v);
}
__device__ __forceinline__ void ldsm_x4(uint32_t& r0, uint32_t& r1, uint32_t& r2,
                                        uint32_t& r3, uint32_t addr) {
    asm volatile("ldmatrix.sync.aligned.m8n8.x4.shared.b16 {%0,%1,%2,%3}, [%4];"
                 : "=r"(r0), "=r"(r1), "=r"(r2), "=r"(r3) : "r"(addr));
}
__device__ __forceinline__ void mma_bf16(float* c, const uint32_t* a,
                                         uint32_t b0, uint32_t b1) {
    asm volatile(
        "mma.sync.aligned.m16n8k16.row.col.f32.bf16.bf16.f32 "
        "{%0,%1,%2,%3}, {%4,%5,%6,%7}, {%8,%9}, {%0,%1,%2,%3};"
        : "+f"(c[0]), "+f"(c[1]), "+f"(c[2]), "+f"(c[3])
        : "r"(a[0]), "r"(a[1]), "r"(a[2]), "r"(a[3]), "r"(b0), "r"(b1));
}

// ===========================================================================
// Small kernels
// ===========================================================================
__global__ void detect_labels(const int* __restrict__ words, int n_words) {
    int all_zero = 1;
    for (int i = 1; i < 256 && i < n_words; i += 2)
        if (words[i] != 0) { all_zero = 0; break; }
    g_lab64 = all_zero;
}

__global__ void zero_kernel() {
    int i = blockIdx.x * blockDim.x + threadIdx.x;
    if (i < MAX_C * D_DIM) g_sums[i] = 0.0f;
    if (i < MAX_C)         g_cnt[i]  = 0.0f;
}

__global__ void __launch_bounds__(128) normalize_scatter(
    const float* __restrict__ feats, const void* __restrict__ labels, int Ccls)
{
    const int row = blockIdx.x;
    const int t   = threadIdx.x;

    const float4 v = reinterpret_cast<const float4*>(feats + (size_t)row * D_DIM)[t];
    float ss = v.x * v.x + v.y * v.y + v.z * v.z + v.w * v.w;
    #pragma unroll
    for (int o = 16; o > 0; o >>= 1) ss += __shfl_xor_sync(0xffffffffu, ss, o);
    __shared__ float warp_ss[4];
    if ((t & 31) == 0) warp_ss[t >> 5] = ss;
    __syncthreads();
    const float tot = warp_ss[0] + warp_ss[1] + warp_ss[2] + warp_ss[3];
    const float inv = 1.0f / fmaxf(sqrtf(tot), 1e-12f);
    if (t == 0) g_inv[row] = inv;

    int lab;
    if (g_lab64) lab = (int)reinterpret_cast<const long long*>(labels)[row];
    else         lab = reinterpret_cast<const int*>(labels)[row];
    if (lab < 0) lab = 0;
    if (lab >= Ccls) lab = Ccls - 1;

    float* s = g_sums + (size_t)lab * D_DIM + t * 4;
    // vectorized reduction (PTX 8.1, sm_90+): 1 op instead of 4 scalar atomics
    asm volatile("red.global.add.v4.f32 [%0], {%1, %2, %3, %4};"
                 :: "l"(s), "f"(v.x * inv), "f"(v.y * inv),
                    "f"(v.z * inv), "f"(v.w * inv) : "memory");
    if (t == 0) atomicAdd(&g_cnt[lab], 1.0f);
}

__global__ void __launch_bounds__(128) proto_update(const float* __restrict__ protos)
{
    const int c = blockIdx.x;
    const int t = threadIdx.x;
    const float cnt   = g_cnt[c];
    const float denom = fmaxf(cnt, 1.0f);

    const float4 p = reinterpret_cast<const float4*>(protos + (size_t)c * D_DIM)[t];
    const float4 s = reinterpret_cast<const float4*>(g_sums  + (size_t)c * D_DIM)[t];

    float4 m;
    m.x = 0.9f * p.x + 0.1f * (s.x / denom);
    m.y = 0.9f * p.y + 0.1f * (s.y / denom);
    m.z = 0.9f * p.z + 0.1f * (s.z / denom);
    m.w = 0.9f * p.w + 0.1f * (s.w / denom);

    float ss = m.x * m.x + m.y * m.y + m.z * m.z + m.w * m.w;
    #pragma unroll
    for (int o = 16; o > 0; o >>= 1) ss += __shfl_xor_sync(0xffffffffu, ss, o);
    __shared__ float warp_ss[4];
    if ((t & 31) == 0) warp_ss[t >> 5] = ss;
    __syncthreads();
    const float tot = warp_ss[0] + warp_ss[1] + warp_ss[2] + warp_ss[3];
    const float inv = 1.0f / fmaxf(sqrtf(tot), 1e-12f);

    float4 o4;
    if (cnt > 0.0f) {
        o4.x = m.x * inv; o4.y = m.y * inv; o4.z = m.z * inv; o4.w = m.w * inv;
    } else {
        o4 = p;
    }
    reinterpret_cast<float4*>(g_protos + (size_t)c * D_DIM)[t] = o4;
}

// ===========================================================================
// GEMM via mma.sync bf16 (hi/lo split -> fp32 accuracy on tensor pipe)
// sim[N,C] = (feats*g_inv) @ g_protos^T.  BM=BN=128, KCH=64, 512 thr, 16 warps.
// ===========================================================================
#define GBM 128
#define GBN 128
#define KCH 64
#define NCHUNK (D_DIM / KCH)                 // 8
#define TILE_B 16384                         // one 128x64 bf16 tile
#define STAGE_B (4 * TILE_B)                 // Ahi Alo Bhi Blo
#define SMEM_TOTAL (1024 + 2 * STAGE_B)      // 132096

__device__ __forceinline__ void split_sts(char* hi, char* lo, uint32_t off, float4 v) {
    __nv_bfloat162 h0 = __float22bfloat162_rn(make_float2(v.x, v.y));
    __nv_bfloat162 h1 = __float22bfloat162_rn(make_float2(v.z, v.w));
    float2 h0f = __bfloat1622float2(h0);
    float2 h1f = __bfloat1622float2(h1);
    __nv_bfloat162 l0 = __float22bfloat162_rn(make_float2(v.x - h0f.x, v.y - h0f.y));
    __nv_bfloat162 l1 = __float22bfloat162_rn(make_float2(v.z - h1f.x, v.w - h1f.y));
    *reinterpret_cast<uint2*>(hi + off) = make_uint2(bf2u(h0), bf2u(h1));
    *reinterpret_cast<uint2*>(lo + off) = make_uint2(bf2u(l0), bf2u(l1));
}

__global__ void __launch_bounds__(512, 1) gemm_mma(
    const float* __restrict__ A, float* __restrict__ Cmat, int Ccls)
{
    extern __shared__ char smem[];
    float* sh_inv = reinterpret_cast<float*>(smem);
    const uint32_t sbase = smem_u32(smem);

    const int tid = threadIdx.x;
    const int wid = tid >> 5, l = tid & 31;
    const int wy = wid >> 2, wx = wid & 3;           // 4x4 warps, 32x32 tiles
    const int bm = blockIdx.y * GBM, bn = blockIdx.x * GBN;

    if (tid < GBM) sh_inv[tid] = g_inv[bm + tid];
    __syncthreads();

    // ---- load mapping: q = f4-slot (const), rows rbase+32s ----
    const int q = tid & 15, rbase = tid >> 4;
    float sa[4];
    uint32_t soff[4];
    const float* Ap[4];
    const float* Bp[4];
    #pragma unroll
    for (int s = 0; s < 4; s++) {
        const int r = rbase + 32 * s;
        sa[s]   = sh_inv[r];
        soff[s] = sw128((uint32_t)(r * 128 + q * 8));
        Ap[s] = A        + (size_t)(bm + r) * D_DIM + q * 4;
        Bp[s] = g_protos + (size_t)(bn + r) * D_DIM + q * 4;
    }

    // ---- ldmatrix lane addresses (relative, per kstep/tile added later) ----
    // A: groups g0 rows0-7@k0, g1 rows8-15@k0, g2 rows0-7@k8, g3 rows8-15@k8
    const int a_row = (l & 15);
    const int a_kh  = (l >> 4);
    // B: g0 n0-7@k0, g1 n0-7@k8, g2 n8-15@k0, g3 n8-15@k8
    const int b_row = (l & 7) + (l >> 4) * 8;
    const int b_kh  = (l >> 3) & 1;

    float acc[2][4][4];
    #pragma unroll
    for (int m = 0; m < 2; m++)
        #pragma unroll
        for (int n = 0; n < 4; n++)
            #pragma unroll
            for (int i = 0; i < 4; i++) acc[m][n][i] = 0.0f;

    float4 pa[4], pb[4];
    // prologue: load chunk 0
    #pragma unroll
    for (int s = 0; s < 4; s++) {
        pa[s] = *reinterpret_cast<const float4*>(Ap[s]);
        pb[s] = *reinterpret_cast<const float4*>(Bp[s]);
    }

    for (int c = 0; c < NCHUNK; c++) {
        const uint32_t st = 1024 + (uint32_t)(c & 1) * STAGE_B;
        char* Ahi = smem + st;
        char* Alo = smem + st + TILE_B;
        char* Bhi = smem + st + 2 * TILE_B;
        char* Blo = smem + st + 3 * TILE_B;

        // stage current prefetch
        #pragma unroll
        for (int s = 0; s < 4; s++) {
            float4 v = pa[s];
            v.x *= sa[s]; v.y *= sa[s]; v.z *= sa[s]; v.w *= sa[s];
            split_sts(Ahi, Alo, soff[s], v);
            split_sts(Bhi, Blo, soff[s], pb[s]);
        }
        __syncthreads();

        // prefetch next chunk
        if (c + 1 < NCHUNK) {
            #pragma unroll
            for (int s = 0; s < 4; s++) {
                pa[s] = *reinterpret_cast<const float4*>(Ap[s] + (c + 1) * KCH);
                pb[s] = *reinterpret_cast<const float4*>(Bp[s] + (c + 1) * KCH);
            }
        }

        // ---- compute 4 k16-steps x (hh + hl + lh) ----
        const uint32_t ah_b = sbase + st;
        const uint32_t al_b = sbase + st + TILE_B;
        const uint32_t bh_b = sbase + st + 2 * TILE_B;
        const uint32_t bl_b = sbase + st + 3 * TILE_B;

        #pragma unroll
        for (int ks = 0; ks < 4; ks++) {
            uint32_t ah[2][4], al[2][4], bh[2][4], bl[2][4];
            #pragma unroll
            for (int mb = 0; mb < 2; mb++) {
                const uint32_t off = sw128((uint32_t)(
                    (wy * 32 + mb * 16 + a_row) * 128 + ks * 32 + a_kh * 16));
                ldsm_x4(ah[mb][0], ah[mb][1], ah[mb][2], ah[mb][3], ah_b + off);
                ldsm_x4(al[mb][0], al[mb][1], al[mb][2], al[mb][3], al_b + off);
            }
            #pragma unroll
            for (int nb2 = 0; nb2 < 2; nb2++) {
                const uint32_t off = sw128((uint32_t)(
                    (wx * 32 + nb2 * 16 + b_row) * 128 + ks * 32 + b_kh * 16));
                ldsm_x4(bh[nb2][0], bh[nb2][1], bh[nb2][2], bh[nb2][3], bh_b + off);
                ldsm_x4(bl[nb2][0], bl[nb2][1], bl[nb2][2], bl[nb2][3], bl_b + off);
            }
            #pragma unroll
            for (int mb = 0; mb < 2; mb++)
                #pragma unroll
                for (int nb2 = 0; nb2 < 2; nb2++)
                    #pragma unroll
                    for (int h = 0; h < 2; h++) {
                        float* cc = acc[mb][nb2 * 2 + h];
                        mma_bf16(cc, ah[mb], bh[nb2][h * 2], bh[nb2][h * 2 + 1]);
                        mma_bf16(cc, ah[mb], bl[nb2][h * 2], bl[nb2][h * 2 + 1]);
                        mma_bf16(cc, al[mb], bh[nb2][h * 2], bh[nb2][h * 2 + 1]);
                    }
        }
        __syncthreads();
    }

    // ---- epilogue: c0,c1 -> (row, col..col+1); c2,c3 -> (row+8, ...) ----
    #pragma unroll
    for (int mb = 0; mb < 2; mb++) {
        const int row = bm + wy * 32 + mb * 16 + (l >> 2);
        #pragma unroll
        for (int nb = 0; nb < 4; nb++) {
            const int col = bn + wx * 32 + nb * 8 + (l & 3) * 2;
            float* o0 = Cmat + (size_t)row * Ccls + col;
            float* o1 = o0 + (size_t)8 * Ccls;
            *reinterpret_cast<float2*>(o0) = make_float2(acc[mb][nb][0], acc[mb][nb][1]);
            *reinterpret_cast<float2*>(o1) = make_float2(acc[mb][nb][2], acc[mb][nb][3]);
        }
    }
}

// ---------------------------------------------------------------------------
extern "C" void kernel_launch(void* const* d_in, const int* in_sizes, int n_in,
                              void* d_out, int out_size)
{
    int i_feats = 0, i_protos = 0, i_labels = 0;
    for (int i = 1; i < n_in; i++) {
        if (in_sizes[i] > in_sizes[i_feats])  i_feats  = i;
        if (in_sizes[i] < in_sizes[i_labels]) i_labels = i;
    }
    for (int i = 0; i < n_in; i++)
        if (i != i_feats && i != i_labels) i_protos = i;

    const float* feats  = (const float*)d_in[i_feats];
    const float* protos = (const float*)d_in[i_protos];
    const void*  labels = d_in[i_labels];

    const int N = in_sizes[i_labels];
    const int C = in_sizes[i_protos] / D_DIM;
    float* out = (float*)d_out;

    detect_labels<<<1, 1>>>((const int*)labels, N);
    {
        int total = MAX_C * D_DIM;
        zero_kernel<<<(total + 255) / 256, 256>>>();
    }
    normalize_scatter<<<N, 128>>>(feats, labels, C);
    proto_update<<<C, 128>>>(protos);

    static bool smem_set = false;
    if (!smem_set) {
        cudaFuncSetAttribute(gemm_mma, cudaFuncAttributeMaxDynamicSharedMemorySize,
                             SMEM_TOTAL);
        smem_set = true;
    }
    dim3 grid(C / GBN, N / GBM);   // (8, 512)
    gemm_mma<<<grid, 512, SMEM_TOTAL>>>(feats, out, C);
}

// round 6
// speedup vs baseline: 2.8250x; 1.1168x over previous
#include <cuda_runtime.h>
#include <cuda_bf16.h>
#include <math.h>
#include <stdint.h>

#define D_DIM 512
#define MAX_N 65536
#define MAX_C 1024

// Scratch (allocation-free rule). Referenced ONLY from device code.
__device__ float g_inv[MAX_N];
__device__ float g_sums[MAX_C * D_DIM];
__device__ float g_cnt[MAX_C];
__device__ float g_protos[MAX_C * D_DIM];
__device__ int   g_lab64;
// Precomputed bf16 hi/lo operands for the tensor-core GEMM
__device__ __nv_bfloat16 g_Ahi[MAX_N * D_DIM];   // 64 MB
__device__ __nv_bfloat16 g_Alo[MAX_N * D_DIM];   // 64 MB
__device__ __nv_bfloat16 g_Bhi[MAX_C * D_DIM];   // 1 MB
__device__ __nv_bfloat16 g_Blo[MAX_C * D_DIM];   // 1 MB

// ---------------------------------------------------------------------------
__device__ __forceinline__ uint32_t smem_u32(const void* p) {
    uint32_t a;
    asm("{ .reg .u64 t; cvta.to.shared.u64 t, %1; cvt.u32.u64 %0, t; }"
        : "=r"(a) : "l"(p));
    return a;
}
__device__ __forceinline__ uint32_t sw128(uint32_t off) { return off ^ ((off >> 3) & 0x70); }
__device__ __forceinline__ uint32_t bf2u(__nv_bfloat162 v) {
    return *reinterpret_cast<uint32_t*>(&v);
}
__device__ __forceinline__ void ldsm_x4(uint32_t& r0, uint32_t& r1, uint32_t& r2,
                                        uint32_t& r3, uint32_t addr) {
    asm volatile("ldmatrix.sync.aligned.m8n8.x4.shared.b16 {%0,%1,%2,%3}, [%4];"
                 : "=r"(r0), "=r"(r1), "=r"(r2), "=r"(r3) : "r"(addr));
}
__device__ __forceinline__ void mma_bf16(float* c, const uint32_t* a,
                                         uint32_t b0, uint32_t b1) {
    asm volatile(
        "mma.sync.aligned.m16n8k16.row.col.f32.bf16.bf16.f32 "
        "{%0,%1,%2,%3}, {%4,%5,%6,%7}, {%8,%9}, {%0,%1,%2,%3};"
        : "+f"(c[0]), "+f"(c[1]), "+f"(c[2]), "+f"(c[3])
        : "r"(a[0]), "r"(a[1]), "r"(a[2]), "r"(a[3]), "r"(b0), "r"(b1));
}
__device__ __forceinline__ void cp16(uint32_t dst, const void* src) {
    asm volatile("cp.async.cg.shared.global [%0], [%1], 16;"
                 :: "r"(dst), "l"(src) : "memory");
}
__device__ __forceinline__ void cp_commit() {
    asm volatile("cp.async.commit_group;" ::: "memory");
}
template <int N>
__device__ __forceinline__ void cp_wait() {
    asm volatile("cp.async.wait_group %0;" :: "n"(N) : "memory");
}
// Split fp32x4 -> bf16 hi / lo pairs
__device__ __forceinline__ void split4(float4 v, uint2& hi, uint2& lo) {
    __nv_bfloat162 h0 = __float22bfloat162_rn(make_float2(v.x, v.y));
    __nv_bfloat162 h1 = __float22bfloat162_rn(make_float2(v.z, v.w));
    float2 h0f = __bfloat1622float2(h0);
    float2 h1f = __bfloat1622float2(h1);
    __nv_bfloat162 l0 = __float22bfloat162_rn(make_float2(v.x - h0f.x, v.y - h0f.y));
    __nv_bfloat162 l1 = __float22bfloat162_rn(make_float2(v.z - h1f.x, v.w - h1f.y));
    hi = make_uint2(bf2u(h0), bf2u(h1));
    lo = make_uint2(bf2u(l0), bf2u(l1));
}

// ===========================================================================
// zero + label-dtype detect (fused; also shifts gemm into the ncu slot)
// ===========================================================================
__global__ void zero_detect(const int* __restrict__ words, int n_words) {
    int i = blockIdx.x * blockDim.x + threadIdx.x;
    if (i < MAX_C * D_DIM) g_sums[i] = 0.0f;
    if (i < MAX_C)         g_cnt[i]  = 0.0f;
    if (i == 0) {
        int all_zero = 1;
        for (int k = 1; k < 256 && k < n_words; k += 2)
            if (words[k] != 0) { all_zero = 0; break; }
        g_lab64 = all_zero;
    }
}

// ===========================================================================
// Per-row L2 norm + segment scatter + emit bf16 hi/lo of normalized feats
// ===========================================================================
__global__ void __launch_bounds__(128) normalize_scatter(
    const float* __restrict__ feats, const void* __restrict__ labels, int Ccls)
{
    const int row = blockIdx.x;
    const int t   = threadIdx.x;

    const float4 v = reinterpret_cast<const float4*>(feats + (size_t)row * D_DIM)[t];
    float ss = v.x * v.x + v.y * v.y + v.z * v.z + v.w * v.w;
    #pragma unroll
    for (int o = 16; o > 0; o >>= 1) ss += __shfl_xor_sync(0xffffffffu, ss, o);
    __shared__ float warp_ss[4];
    if ((t & 31) == 0) warp_ss[t >> 5] = ss;
    __syncthreads();
    const float tot = warp_ss[0] + warp_ss[1] + warp_ss[2] + warp_ss[3];
    const float inv = 1.0f / fmaxf(sqrtf(tot), 1e-12f);
    if (t == 0) g_inv[row] = inv;

    float4 f = make_float4(v.x * inv, v.y * inv, v.z * inv, v.w * inv);

    // emit bf16 hi/lo of normalized row
    uint2 hi, lo;
    split4(f, hi, lo);
    const size_t e = (size_t)row * D_DIM + t * 4;
    *reinterpret_cast<uint2*>(reinterpret_cast<char*>(g_Ahi) + e * 2) = hi;
    *reinterpret_cast<uint2*>(reinterpret_cast<char*>(g_Alo) + e * 2) = lo;

    int lab;
    if (g_lab64) lab = (int)reinterpret_cast<const long long*>(labels)[row];
    else         lab = reinterpret_cast<const int*>(labels)[row];
    if (lab < 0) lab = 0;
    if (lab >= Ccls) lab = Ccls - 1;

    float* s = g_sums + (size_t)lab * D_DIM + t * 4;
    asm volatile("red.global.add.v4.f32 [%0], {%1, %2, %3, %4};"
                 :: "l"(s), "f"(f.x), "f"(f.y), "f"(f.z), "f"(f.w) : "memory");
    if (t == 0) atomicAdd(&g_cnt[lab], 1.0f);
}

// ===========================================================================
// Prototype EMA + renorm + emit bf16 hi/lo of the updated bank
// ===========================================================================
__global__ void __launch_bounds__(128) proto_update(const float* __restrict__ protos)
{
    const int c = blockIdx.x;
    const int t = threadIdx.x;
    const float cnt   = g_cnt[c];
    const float denom = fmaxf(cnt, 1.0f);

    const float4 p = reinterpret_cast<const float4*>(protos + (size_t)c * D_DIM)[t];
    const float4 s = reinterpret_cast<const float4*>(g_sums  + (size_t)c * D_DIM)[t];

    float4 m;
    m.x = 0.9f * p.x + 0.1f * (s.x / denom);
    m.y = 0.9f * p.y + 0.1f * (s.y / denom);
    m.z = 0.9f * p.z + 0.1f * (s.z / denom);
    m.w = 0.9f * p.w + 0.1f * (s.w / denom);

    float ss = m.x * m.x + m.y * m.y + m.z * m.z + m.w * m.w;
    #pragma unroll
    for (int o = 16; o > 0; o >>= 1) ss += __shfl_xor_sync(0xffffffffu, ss, o);
    __shared__ float warp_ss[4];
    if ((t & 31) == 0) warp_ss[t >> 5] = ss;
    __syncthreads();
    const float tot = warp_ss[0] + warp_ss[1] + warp_ss[2] + warp_ss[3];
    const float inv = 1.0f / fmaxf(sqrtf(tot), 1e-12f);

    float4 o4;
    if (cnt > 0.0f) {
        o4.x = m.x * inv; o4.y = m.y * inv; o4.z = m.z * inv; o4.w = m.w * inv;
    } else {
        o4 = p;
    }
    reinterpret_cast<float4*>(g_protos + (size_t)c * D_DIM)[t] = o4;

    uint2 hi, lo;
    split4(o4, hi, lo);
    const size_t e = (size_t)c * D_DIM + t * 4;
    *reinterpret_cast<uint2*>(reinterpret_cast<char*>(g_Bhi) + e * 2) = hi;
    *reinterpret_cast<uint2*>(reinterpret_cast<char*>(g_Blo) + e * 2) = lo;
}

// ===========================================================================
// GEMM: sim = Anorm @ P'^T via mma.sync bf16 hi/lo (3-term), operands
// precomputed in gmem as bf16. cp.async 3-stage pipeline.
// BM=BN=128, KCH=64, 512 threads (16 warps, 4x4 of 32x32 tiles).
// ===========================================================================
#define GBM 128
#define GBN 128
#define KCH 64
#define NCHUNK (D_DIM / KCH)                 // 8
#define TILE_B 16384                         // 128x64 bf16
#define STAGE_B (4 * TILE_B)                 // Ahi Alo Bhi Blo = 64KB
#define NSTAGE 3
#define SMEM_TOTAL (NSTAGE * STAGE_B)        // 196608

__global__ void __launch_bounds__(512, 1) gemm_mma(
    float* __restrict__ Cmat, int Ccls)
{
    extern __shared__ char smem[];
    const uint32_t sbase = smem_u32(smem);

    const int tid = threadIdx.x;
    const int wid = tid >> 5, l = tid & 31;
    const int wy = wid >> 2, wx = wid & 3;
    const int bm = blockIdx.y * GBM, bn = blockIdx.x * GBN;

    // ---- cp.async fill mapping: thread -> 2 rows per tile, 16B seg q ----
    const int q = tid & 7;            // 16B segment within 128B row
    const int r0 = tid >> 3;          // 0..63
    const uint32_t d0 = sw128((uint32_t)(r0 * 128 + q * 16));
    const uint32_t d1 = sw128((uint32_t)((r0 + 64) * 128 + q * 16));

    const char* srcAh0 = reinterpret_cast<const char*>(g_Ahi) + ((size_t)(bm + r0)      * D_DIM + q * 8) * 2;
    const char* srcAh1 = reinterpret_cast<const char*>(g_Ahi) + ((size_t)(bm + r0 + 64) * D_DIM + q * 8) * 2;
    const char* srcAl0 = reinterpret_cast<const char*>(g_Alo) + ((size_t)(bm + r0)      * D_DIM + q * 8) * 2;
    const char* srcAl1 = reinterpret_cast<const char*>(g_Alo) + ((size_t)(bm + r0 + 64) * D_DIM + q * 8) * 2;
    const char* srcBh0 = reinterpret_cast<const char*>(g_Bhi) + ((size_t)(bn + r0)      * D_DIM + q * 8) * 2;
    const char* srcBh1 = reinterpret_cast<const char*>(g_Bhi) + ((size_t)(bn + r0 + 64) * D_DIM + q * 8) * 2;
    const char* srcBl0 = reinterpret_cast<const char*>(g_Blo) + ((size_t)(bn + r0)      * D_DIM + q * 8) * 2;
    const char* srcBl1 = reinterpret_cast<const char*>(g_Blo) + ((size_t)(bn + r0 + 64) * D_DIM + q * 8) * 2;

    auto issue_stage = [&](int c) {
        const uint32_t st = sbase + (uint32_t)(c % NSTAGE) * STAGE_B;
        const int koff = c * KCH * 2;   // byte offset along K in gmem rows
        cp16(st               + d0, srcAh0 + koff);
        cp16(st               + d1, srcAh1 + koff);
        cp16(st +     TILE_B  + d0, srcAl0 + koff);
        cp16(st +     TILE_B  + d1, srcAl1 + koff);
        cp16(st + 2 * TILE_B  + d0, srcBh0 + koff);
        cp16(st + 2 * TILE_B  + d1, srcBh1 + koff);
        cp16(st + 3 * TILE_B  + d0, srcBl0 + koff);
        cp16(st + 3 * TILE_B  + d1, srcBl1 + koff);
        cp_commit();
    };

    // ---- ldmatrix lane addressing (validated in R5) ----
    const int a_row = (l & 15);
    const int a_kh  = (l >> 4);
    const int b_row = (l & 7) + (l >> 4) * 8;
    const int b_kh  = (l >> 3) & 1;

    float acc[2][4][4];
    #pragma unroll
    for (int m = 0; m < 2; m++)
        #pragma unroll
        for (int n = 0; n < 4; n++)
            #pragma unroll
            for (int i = 0; i < 4; i++) acc[m][n][i] = 0.0f;

    issue_stage(0);
    issue_stage(1);

    for (int c = 0; c < NCHUNK; c++) {
        cp_wait<1>();          // stage c complete (one newer group may pend)
        __syncthreads();

        const uint32_t st = sbase + (uint32_t)(c % NSTAGE) * STAGE_B;
        const uint32_t ah_b = st;
        const uint32_t al_b = st + TILE_B;
        const uint32_t bh_b = st + 2 * TILE_B;
        const uint32_t bl_b = st + 3 * TILE_B;

        #pragma unroll
        for (int ks = 0; ks < 4; ks++) {
            uint32_t ah[2][4], al[2][4], bh[2][4], bl[2][4];
            #pragma unroll
            for (int mb = 0; mb < 2; mb++) {
                const uint32_t off = sw128((uint32_t)(
                    (wy * 32 + mb * 16 + a_row) * 128 + ks * 32 + a_kh * 16));
                ldsm_x4(ah[mb][0], ah[mb][1], ah[mb][2], ah[mb][3], ah_b + off);
                ldsm_x4(al[mb][0], al[mb][1], al[mb][2], al[mb][3], al_b + off);
            }
            #pragma unroll
            for (int nb2 = 0; nb2 < 2; nb2++) {
                const uint32_t off = sw128((uint32_t)(
                    (wx * 32 + nb2 * 16 + b_row) * 128 + ks * 32 + b_kh * 16));
                ldsm_x4(bh[nb2][0], bh[nb2][1], bh[nb2][2], bh[nb2][3], bh_b + off);
                ldsm_x4(bl[nb2][0], bl[nb2][1], bl[nb2][2], bl[nb2][3], bl_b + off);
            }
            #pragma unroll
            for (int mb = 0; mb < 2; mb++)
                #pragma unroll
                for (int nb2 = 0; nb2 < 2; nb2++)
                    #pragma unroll
                    for (int h = 0; h < 2; h++) {
                        float* cc = acc[mb][nb2 * 2 + h];
                        mma_bf16(cc, ah[mb], bh[nb2][h * 2], bh[nb2][h * 2 + 1]);
                        mma_bf16(cc, ah[mb], bl[nb2][h * 2], bl[nb2][h * 2 + 1]);
                        mma_bf16(cc, al[mb], bh[nb2][h * 2], bh[nb2][h * 2 + 1]);
                    }
        }
        __syncthreads();       // all reads of stage c done before refill
        if (c + 2 < NCHUNK) issue_stage(c + 2);
    }

    // ---- epilogue ----
    #pragma unroll
    for (int mb = 0; mb < 2; mb++) {
        const int row = bm + wy * 32 + mb * 16 + (l >> 2);
        #pragma unroll
        for (int nb = 0; nb < 4; nb++) {
            const int col = bn + wx * 32 + nb * 8 + (l & 3) * 2;
            float* o0 = Cmat + (size_t)row * Ccls + col;
            float* o1 = o0 + (size_t)8 * Ccls;
            *reinterpret_cast<float2*>(o0) = make_float2(acc[mb][nb][0], acc[mb][nb][1]);
            *reinterpret_cast<float2*>(o1) = make_float2(acc[mb][nb][2], acc[mb][nb][3]);
        }
    }
}

// ---------------------------------------------------------------------------
extern "C" void kernel_launch(void* const* d_in, const int* in_sizes, int n_in,
                              void* d_out, int out_size)
{
    int i_feats = 0, i_protos = 0, i_labels = 0;
    for (int i = 1; i < n_in; i++) {
        if (in_sizes[i] > in_sizes[i_feats])  i_feats  = i;
        if (in_sizes[i] < in_sizes[i_labels]) i_labels = i;
    }
    for (int i = 0; i < n_in; i++)
        if (i != i_feats && i != i_labels) i_protos = i;

    const float* feats  = (const float*)d_in[i_feats];
    const float* protos = (const float*)d_in[i_protos];
    const void*  labels = d_in[i_labels];

    const int N = in_sizes[i_labels];
    const int C = in_sizes[i_protos] / D_DIM;
    float* out = (float*)d_out;

    {
        int total = MAX_C * D_DIM;
        zero_detect<<<(total + 255) / 256, 256>>>((const int*)labels, N);
    }
    normalize_scatter<<<N, 128>>>(feats, labels, C);
    proto_update<<<C, 128>>>(protos);

    static bool smem_set = false;
    if (!smem_set) {
        cudaFuncSetAttribute(gemm_mma, cudaFuncAttributeMaxDynamicSharedMemorySize,
                             SMEM_TOTAL);
        smem_set = true;
    }
    dim3 grid(C / GBN, N / GBM);   // (8, 512)
    gemm_mma<<<grid, 512, SMEM_TOTAL>>>(out, C);
}

// round 7
// speedup vs baseline: 3.9540x; 1.3996x over previous
#include <cuda_runtime.h>
#include <cuda_bf16.h>
#include <cuda_fp16.h>
#include <math.h>
#include <stdint.h>

#define D_DIM 512
#define MAX_N 65536
#define MAX_C 1024

// Scratch (allocation-free rule). Referenced ONLY from device code.
__device__ float g_inv[MAX_N];
__device__ float g_sums[MAX_C * D_DIM];
__device__ float g_cnt[MAX_C];
__device__ float g_protos[MAX_C * D_DIM];
__device__ int   g_lab64;
// Precomputed fp16 operands for the tensor-core GEMM
__device__ __half g_Ahi[MAX_N * D_DIM];   // 64 MB
__device__ __half g_Alo[MAX_N * D_DIM];   // 64 MB
__device__ __half g_Bh [MAX_C * D_DIM];   // 1 MB

// ---------------------------------------------------------------------------
__device__ __forceinline__ uint32_t smem_u32(const void* p) {
    uint32_t a;
    asm("{ .reg .u64 t; cvta.to.shared.u64 t, %1; cvt.u32.u64 %0, t; }"
        : "=r"(a) : "l"(p));
    return a;
}
__device__ __forceinline__ uint32_t sw128(uint32_t off) { return off ^ ((off >> 3) & 0x70); }
__device__ __forceinline__ uint32_t h2u(__half2 v) {
    return *reinterpret_cast<uint32_t*>(&v);
}
__device__ __forceinline__ void ldsm_x4(uint32_t& r0, uint32_t& r1, uint32_t& r2,
                                        uint32_t& r3, uint32_t addr) {
    asm volatile("ldmatrix.sync.aligned.m8n8.x4.shared.b16 {%0,%1,%2,%3}, [%4];"
                 : "=r"(r0), "=r"(r1), "=r"(r2), "=r"(r3) : "r"(addr));
}
__device__ __forceinline__ void mma_f16(float* c, const uint32_t* a,
                                        uint32_t b0, uint32_t b1) {
    asm volatile(
        "mma.sync.aligned.m16n8k16.row.col.f32.f16.f16.f32 "
        "{%0,%1,%2,%3}, {%4,%5,%6,%7}, {%8,%9}, {%0,%1,%2,%3};"
        : "+f"(c[0]), "+f"(c[1]), "+f"(c[2]), "+f"(c[3])
        : "r"(a[0]), "r"(a[1]), "r"(a[2]), "r"(a[3]), "r"(b0), "r"(b1));
}
__device__ __forceinline__ void cp16(uint32_t dst, const void* src) {
    asm volatile("cp.async.cg.shared.global [%0], [%1], 16;"
                 :: "r"(dst), "l"(src) : "memory");
}
__device__ __forceinline__ void cp_commit() {
    asm volatile("cp.async.commit_group;" ::: "memory");
}
template <int N>
__device__ __forceinline__ void cp_wait() {
    asm volatile("cp.async.wait_group %0;" :: "n"(N) : "memory");
}
// Split fp32x4 -> fp16 hi / lo pairs
__device__ __forceinline__ void split4h(float4 v, uint2& hi, uint2& lo) {
    __half2 h0 = __float22half2_rn(make_float2(v.x, v.y));
    __half2 h1 = __float22half2_rn(make_float2(v.z, v.w));
    float2 h0f = __half22float2(h0);
    float2 h1f = __half22float2(h1);
    __half2 l0 = __float22half2_rn(make_float2(v.x - h0f.x, v.y - h0f.y));
    __half2 l1 = __float22half2_rn(make_float2(v.z - h1f.x, v.w - h1f.y));
    hi = make_uint2(h2u(h0), h2u(h1));
    lo = make_uint2(h2u(l0), h2u(l1));
}

// ===========================================================================
// zero + label-dtype detect (fused)
// ===========================================================================
__global__ void zero_detect(const int* __restrict__ words, int n_words) {
    int i = blockIdx.x * blockDim.x + threadIdx.x;
    if (i < MAX_C * D_DIM) g_sums[i] = 0.0f;
    if (i < MAX_C)         g_cnt[i]  = 0.0f;
    if (i == 0) {
        int all_zero = 1;
        for (int k = 1; k < 256 && k < n_words; k += 2)
            if (words[k] != 0) { all_zero = 0; break; }
        g_lab64 = all_zero;
    }
}

// ===========================================================================
// Per-row L2 norm + segment scatter + emit fp16 hi/lo of normalized feats
// ===========================================================================
__global__ void __launch_bounds__(128) normalize_scatter(
    const float* __restrict__ feats, const void* __restrict__ labels, int Ccls)
{
    const int row = blockIdx.x;
    const int t   = threadIdx.x;

    const float4 v = reinterpret_cast<const float4*>(feats + (size_t)row * D_DIM)[t];
    float ss = v.x * v.x + v.y * v.y + v.z * v.z + v.w * v.w;
    #pragma unroll
    for (int o = 16; o > 0; o >>= 1) ss += __shfl_xor_sync(0xffffffffu, ss, o);
    __shared__ float warp_ss[4];
    if ((t & 31) == 0) warp_ss[t >> 5] = ss;
    __syncthreads();
    const float tot = warp_ss[0] + warp_ss[1] + warp_ss[2] + warp_ss[3];
    const float inv = 1.0f / fmaxf(sqrtf(tot), 1e-12f);
    if (t == 0) g_inv[row] = inv;

    float4 f = make_float4(v.x * inv, v.y * inv, v.z * inv, v.w * inv);

    uint2 hi, lo;
    split4h(f, hi, lo);
    const size_t e = (size_t)row * D_DIM + t * 4;
    *reinterpret_cast<uint2*>(reinterpret_cast<char*>(g_Ahi) + e * 2) = hi;
    *reinterpret_cast<uint2*>(reinterpret_cast<char*>(g_Alo) + e * 2) = lo;

    int lab;
    if (g_lab64) lab = (int)reinterpret_cast<const long long*>(labels)[row];
    else         lab = reinterpret_cast<const int*>(labels)[row];
    if (lab < 0) lab = 0;
    if (lab >= Ccls) lab = Ccls - 1;

    float* s = g_sums + (size_t)lab * D_DIM + t * 4;
    asm volatile("red.global.add.v4.f32 [%0], {%1, %2, %3, %4};"
                 :: "l"(s), "f"(f.x), "f"(f.y), "f"(f.z), "f"(f.w) : "memory");
    if (t == 0) atomicAdd(&g_cnt[lab], 1.0f);
}

// ===========================================================================
// Prototype EMA + renorm + emit fp16 of the updated bank
// ===========================================================================
__global__ void __launch_bounds__(128) proto_update(const float* __restrict__ protos)
{
    const int c = blockIdx.x;
    const int t = threadIdx.x;
    const float cnt   = g_cnt[c];
    const float denom = fmaxf(cnt, 1.0f);

    const float4 p = reinterpret_cast<const float4*>(protos + (size_t)c * D_DIM)[t];
    const float4 s = reinterpret_cast<const float4*>(g_sums  + (size_t)c * D_DIM)[t];

    float4 m;
    m.x = 0.9f * p.x + 0.1f * (s.x / denom);
    m.y = 0.9f * p.y + 0.1f * (s.y / denom);
    m.z = 0.9f * p.z + 0.1f * (s.z / denom);
    m.w = 0.9f * p.w + 0.1f * (s.w / denom);

    float ss = m.x * m.x + m.y * m.y + m.z * m.z + m.w * m.w;
    #pragma unroll
    for (int o = 16; o > 0; o >>= 1) ss += __shfl_xor_sync(0xffffffffu, ss, o);
    __shared__ float warp_ss[4];
    if ((t & 31) == 0) warp_ss[t >> 5] = ss;
    __syncthreads();
    const float tot = warp_ss[0] + warp_ss[1] + warp_ss[2] + warp_ss[3];
    const float inv = 1.0f / fmaxf(sqrtf(tot), 1e-12f);

    float4 o4;
    if (cnt > 0.0f) {
        o4.x = m.x * inv; o4.y = m.y * inv; o4.z = m.z * inv; o4.w = m.w * inv;
    } else {
        o4 = p;
    }
    reinterpret_cast<float4*>(g_protos + (size_t)c * D_DIM)[t] = o4;

    __half2 b0 = __float22half2_rn(make_float2(o4.x, o4.y));
    __half2 b1 = __float22half2_rn(make_float2(o4.z, o4.w));
    const size_t e = (size_t)c * D_DIM + t * 4;
    *reinterpret_cast<uint2*>(reinterpret_cast<char*>(g_Bh) + e * 2) =
        make_uint2(h2u(b0), h2u(b1));
}

// ===========================================================================
// GEMM: sim = Anorm @ P'^T via mma.sync fp16, 2-term (Ahi + Alo) x Bh.
// BM=BN=128, KCH=64, 512 threads (16 warps, 4x4 of 32x32 tiles).
// 4-stage cp.async pipeline, one __syncthreads per chunk.
// ===========================================================================
#define GBM 128
#define GBN 128
#define KCH 64
#define NCHUNK (D_DIM / KCH)                 // 8
#define TILE_B 16384                         // 128x64 fp16
#define STAGE_B (3 * TILE_B)                 // Ahi Alo Bh = 48KB
#define NSTAGE 4
#define SMEM_TOTAL (NSTAGE * STAGE_B)        // 196608

__global__ void __launch_bounds__(512, 1) gemm_mma(
    float* __restrict__ Cmat, int Ccls)
{
    extern __shared__ char smem[];
    const uint32_t sbase = smem_u32(smem);

    const int tid = threadIdx.x;
    const int wid = tid >> 5, l = tid & 31;
    const int wy = wid >> 2, wx = wid & 3;
    const int bm = blockIdx.y * GBM, bn = blockIdx.x * GBN;

    // ---- cp.async fill mapping: 2 rows per tile per thread, 16B segment ----
    const int q = tid & 7;
    const int r0 = tid >> 3;          // 0..63
    const uint32_t d0 = sw128((uint32_t)(r0 * 128 + q * 16));
    const uint32_t d1 = sw128((uint32_t)((r0 + 64) * 128 + q * 16));

    const char* srcAh0 = reinterpret_cast<const char*>(g_Ahi) + ((size_t)(bm + r0)      * D_DIM + q * 8) * 2;
    const char* srcAh1 = reinterpret_cast<const char*>(g_Ahi) + ((size_t)(bm + r0 + 64) * D_DIM + q * 8) * 2;
    const char* srcAl0 = reinterpret_cast<const char*>(g_Alo) + ((size_t)(bm + r0)      * D_DIM + q * 8) * 2;
    const char* srcAl1 = reinterpret_cast<const char*>(g_Alo) + ((size_t)(bm + r0 + 64) * D_DIM + q * 8) * 2;
    const char* srcBh0 = reinterpret_cast<const char*>(g_Bh ) + ((size_t)(bn + r0)      * D_DIM + q * 8) * 2;
    const char* srcBh1 = reinterpret_cast<const char*>(g_Bh ) + ((size_t)(bn + r0 + 64) * D_DIM + q * 8) * 2;

    auto issue_stage = [&](int c) {
        const uint32_t st = sbase + (uint32_t)(c % NSTAGE) * STAGE_B;
        const int koff = c * KCH * 2;
        cp16(st              + d0, srcAh0 + koff);
        cp16(st              + d1, srcAh1 + koff);
        cp16(st +     TILE_B + d0, srcAl0 + koff);
        cp16(st +     TILE_B + d1, srcAl1 + koff);
        cp16(st + 2 * TILE_B + d0, srcBh0 + koff);
        cp16(st + 2 * TILE_B + d1, srcBh1 + koff);
        cp_commit();
    };

    // ---- ldmatrix lane addressing (validated R5/R6) ----
    const int a_row = (l & 15);
    const int a_kh  = (l >> 4);
    const int b_row = (l & 7) + (l >> 4) * 8;
    const int b_kh  = (l >> 3) & 1;

    float acc[2][4][4];
    #pragma unroll
    for (int m = 0; m < 2; m++)
        #pragma unroll
        for (int n = 0; n < 4; n++)
            #pragma unroll
            for (int i = 0; i < 4; i++) acc[m][n][i] = 0.0f;

    issue_stage(0);
    issue_stage(1);
    issue_stage(2);

    for (int c = 0; c < NCHUNK; c++) {
        cp_wait<2>();          // oldest (stage c) complete
        __syncthreads();       // also guarantees stage c-1 fully consumed
        if (c + 3 < NCHUNK) issue_stage(c + 3);

        const uint32_t st = sbase + (uint32_t)(c % NSTAGE) * STAGE_B;
        const uint32_t ah_b = st;
        const uint32_t al_b = st + TILE_B;
        const uint32_t bh_b = st + 2 * TILE_B;

        #pragma unroll
        for (int ks = 0; ks < 4; ks++) {
            uint32_t ah[2][4], al[2][4], bh[2][4];
            #pragma unroll
            for (int mb = 0; mb < 2; mb++) {
                const uint32_t off = sw128((uint32_t)(
                    (wy * 32 + mb * 16 + a_row) * 128 + ks * 32 + a_kh * 16));
                ldsm_x4(ah[mb][0], ah[mb][1], ah[mb][2], ah[mb][3], ah_b + off);
                ldsm_x4(al[mb][0], al[mb][1], al[mb][2], al[mb][3], al_b + off);
            }
            #pragma unroll
            for (int nb2 = 0; nb2 < 2; nb2++) {
                const uint32_t off = sw128((uint32_t)(
                    (wx * 32 + nb2 * 16 + b_row) * 128 + ks * 32 + b_kh * 16));
                ldsm_x4(bh[nb2][0], bh[nb2][1], bh[nb2][2], bh[nb2][3], bh_b + off);
            }
            #pragma unroll
            for (int mb = 0; mb < 2; mb++)
                #pragma unroll
                for (int nb2 = 0; nb2 < 2; nb2++)
                    #pragma unroll
                    for (int h = 0; h < 2; h++) {
                        float* cc = acc[mb][nb2 * 2 + h];
                        mma_f16(cc, ah[mb], bh[nb2][h * 2], bh[nb2][h * 2 + 1]);
                        mma_f16(cc, al[mb], bh[nb2][h * 2], bh[nb2][h * 2 + 1]);
                    }
        }
    }

    // ---- epilogue ----
    #pragma unroll
    for (int mb = 0; mb < 2; mb++) {
        const int row = bm + wy * 32 + mb * 16 + (l >> 2);
        #pragma unroll
        for (int nb = 0; nb < 4; nb++) {
            const int col = bn + wx * 32 + nb * 8 + (l & 3) * 2;
            float* o0 = Cmat + (size_t)row * Ccls + col;
            float* o1 = o0 + (size_t)8 * Ccls;
            *reinterpret_cast<float2*>(o0) = make_float2(acc[mb][nb][0], acc[mb][nb][1]);
            *reinterpret_cast<float2*>(o1) = make_float2(acc[mb][nb][2], acc[mb][nb][3]);
        }
    }
}

// ---------------------------------------------------------------------------
extern "C" void kernel_launch(void* const* d_in, const int* in_sizes, int n_in,
                              void* d_out, int out_size)
{
    int i_feats = 0, i_protos = 0, i_labels = 0;
    for (int i = 1; i < n_in; i++) {
        if (in_sizes[i] > in_sizes[i_feats])  i_feats  = i;
        if (in_sizes[i] < in_sizes[i_labels]) i_labels = i;
    }
    for (int i = 0; i < n_in; i++)
        if (i != i_feats && i != i_labels) i_protos = i;

    const float* feats  = (const float*)d_in[i_feats];
    const float* protos = (const float*)d_in[i_protos];
    const void*  labels = d_in[i_labels];

    const int N = in_sizes[i_labels];
    const int C = in_sizes[i_protos] / D_DIM;
    float* out = (float*)d_out;

    {
        int total = MAX_C * D_DIM;
        zero_detect<<<(total + 255) / 256, 256>>>((const int*)labels, N);
    }
    normalize_scatter<<<N, 128>>>(feats, labels, C);
    proto_update<<<C, 128>>>(protos);

    static bool smem_set = false;
    if (!smem_set) {
        cudaFuncSetAttribute(gemm_mma, cudaFuncAttributeMaxDynamicSharedMemorySize,
                             SMEM_TOTAL);
        smem_set = true;
    }
    dim3 grid(C / GBN, N / GBM);   // (8, 512)
    gemm_mma<<<grid, 512, SMEM_TOTAL>>>(out, C);
}

// round 8
// speedup vs baseline: 6.4482x; 1.6308x over previous
#include <cuda_runtime.h>
#include <cuda_fp16.h>
#include <math.h>
#include <stdint.h>

#define D_DIM 512
#define MAX_N 65536
#define MAX_C 1024

// Scratch (allocation-free rule). Referenced ONLY from device code.
__device__ float g_inv[MAX_N];
__device__ float g_sums[MAX_C * D_DIM];
__device__ float g_cnt[MAX_C];
__device__ float g_protos[MAX_C * D_DIM];
__device__ int   g_lab64;
// Precomputed fp16 operands for the tensor-core GEMM
__device__ __half g_Ah[MAX_N * D_DIM];   // 64 MB
__device__ __half g_Bh[MAX_C * D_DIM];   // 1 MB

// ---------------------------------------------------------------------------
__device__ __forceinline__ uint32_t smem_u32(const void* p) {
    uint32_t a;
    asm("{ .reg .u64 t; cvta.to.shared.u64 t, %1; cvt.u32.u64 %0, t; }"
        : "=r"(a) : "l"(p));
    return a;
}
__device__ __forceinline__ uint32_t sw128(uint32_t off) { return off ^ ((off >> 3) & 0x70); }
__device__ __forceinline__ uint32_t h2u(__half2 v) {
    return *reinterpret_cast<uint32_t*>(&v);
}
__device__ __forceinline__ void ldsm_x4(uint32_t& r0, uint32_t& r1, uint32_t& r2,
                                        uint32_t& r3, uint32_t addr) {
    asm volatile("ldmatrix.sync.aligned.m8n8.x4.shared.b16 {%0,%1,%2,%3}, [%4];"
                 : "=r"(r0), "=r"(r1), "=r"(r2), "=r"(r3) : "r"(addr));
}
__device__ __forceinline__ void mma_f16(float* c, const uint32_t* a,
                                        uint32_t b0, uint32_t b1) {
    asm volatile(
        "mma.sync.aligned.m16n8k16.row.col.f32.f16.f16.f32 "
        "{%0,%1,%2,%3}, {%4,%5,%6,%7}, {%8,%9}, {%0,%1,%2,%3};"
        : "+f"(c[0]), "+f"(c[1]), "+f"(c[2]), "+f"(c[3])
        : "r"(a[0]), "r"(a[1]), "r"(a[2]), "r"(a[3]), "r"(b0), "r"(b1));
}
__device__ __forceinline__ void cp16(uint32_t dst, const void* src) {
    asm volatile("cp.async.cg.shared.global [%0], [%1], 16;"
                 :: "r"(dst), "l"(src) : "memory");
}
__device__ __forceinline__ void cp_commit() {
    asm volatile("cp.async.commit_group;" ::: "memory");
}
template <int N>
__device__ __forceinline__ void cp_wait() {
    asm volatile("cp.async.wait_group %0;" :: "n"(N) : "memory");
}

// ===========================================================================
// zero + label-dtype detect (fused)
// ===========================================================================
__global__ void zero_detect(const int* __restrict__ words, int n_words) {
    int i = blockIdx.x * blockDim.x + threadIdx.x;
    if (i < MAX_C * D_DIM) g_sums[i] = 0.0f;
    if (i < MAX_C)         g_cnt[i]  = 0.0f;
    if (i == 0) {
        int all_zero = 1;
        for (int k = 1; k < 256 && k < n_words; k += 2)
            if (words[k] != 0) { all_zero = 0; break; }
        g_lab64 = all_zero;
    }
}

// ===========================================================================
// Per-row L2 norm + segment scatter + emit fp16 of normalized feats
// ===========================================================================
__global__ void __launch_bounds__(128) normalize_scatter(
    const float* __restrict__ feats, const void* __restrict__ labels, int Ccls)
{
    const int row = blockIdx.x;
    const int t   = threadIdx.x;

    const float4 v = reinterpret_cast<const float4*>(feats + (size_t)row * D_DIM)[t];
    float ss = v.x * v.x + v.y * v.y + v.z * v.z + v.w * v.w;
    #pragma unroll
    for (int o = 16; o > 0; o >>= 1) ss += __shfl_xor_sync(0xffffffffu, ss, o);
    __shared__ float warp_ss[4];
    if ((t & 31) == 0) warp_ss[t >> 5] = ss;
    __syncthreads();
    const float tot = warp_ss[0] + warp_ss[1] + warp_ss[2] + warp_ss[3];
    const float inv = 1.0f / fmaxf(sqrtf(tot), 1e-12f);
    if (t == 0) g_inv[row] = inv;

    float4 f = make_float4(v.x * inv, v.y * inv, v.z * inv, v.w * inv);

    __half2 a0 = __float22half2_rn(make_float2(f.x, f.y));
    __half2 a1 = __float22half2_rn(make_float2(f.z, f.w));
    const size_t e = (size_t)row * D_DIM + t * 4;
    *reinterpret_cast<uint2*>(reinterpret_cast<char*>(g_Ah) + e * 2) =
        make_uint2(h2u(a0), h2u(a1));

    int lab;
    if (g_lab64) lab = (int)reinterpret_cast<const long long*>(labels)[row];
    else         lab = reinterpret_cast<const int*>(labels)[row];
    if (lab < 0) lab = 0;
    if (lab >= Ccls) lab = Ccls - 1;

    float* s = g_sums + (size_t)lab * D_DIM + t * 4;
    asm volatile("red.global.add.v4.f32 [%0], {%1, %2, %3, %4};"
                 :: "l"(s), "f"(f.x), "f"(f.y), "f"(f.z), "f"(f.w) : "memory");
    if (t == 0) atomicAdd(&g_cnt[lab], 1.0f);
}

// ===========================================================================
// Prototype EMA + renorm + emit fp16 of the updated bank
// ===========================================================================
__global__ void __launch_bounds__(128) proto_update(const float* __restrict__ protos)
{
    const int c = blockIdx.x;
    const int t = threadIdx.x;
    const float cnt   = g_cnt[c];
    const float denom = fmaxf(cnt, 1.0f);

    const float4 p = reinterpret_cast<const float4*>(protos + (size_t)c * D_DIM)[t];
    const float4 s = reinterpret_cast<const float4*>(g_sums  + (size_t)c * D_DIM)[t];

    float4 m;
    m.x = 0.9f * p.x + 0.1f * (s.x / denom);
    m.y = 0.9f * p.y + 0.1f * (s.y / denom);
    m.z = 0.9f * p.z + 0.1f * (s.z / denom);
    m.w = 0.9f * p.w + 0.1f * (s.w / denom);

    float ss = m.x * m.x + m.y * m.y + m.z * m.z + m.w * m.w;
    #pragma unroll
    for (int o = 16; o > 0; o >>= 1) ss += __shfl_xor_sync(0xffffffffu, ss, o);
    __shared__ float warp_ss[4];
    if ((t & 31) == 0) warp_ss[t >> 5] = ss;
    __syncthreads();
    const float tot = warp_ss[0] + warp_ss[1] + warp_ss[2] + warp_ss[3];
    const float inv = 1.0f / fmaxf(sqrtf(tot), 1e-12f);

    float4 o4;
    if (cnt > 0.0f) {
        o4.x = m.x * inv; o4.y = m.y * inv; o4.z = m.z * inv; o4.w = m.w * inv;
    } else {
        o4 = p;
    }
    reinterpret_cast<float4*>(g_protos + (size_t)c * D_DIM)[t] = o4;

    __half2 b0 = __float22half2_rn(make_float2(o4.x, o4.y));
    __half2 b1 = __float22half2_rn(make_float2(o4.z, o4.w));
    const size_t e = (size_t)c * D_DIM + t * 4;
    *reinterpret_cast<uint2*>(reinterpret_cast<char*>(g_Bh) + e * 2) =
        make_uint2(h2u(b0), h2u(b1));
}

// ===========================================================================
// GEMM: sim = Ah @ Bh^T, single fp16 term. Block 128x256, KCH=64, 512 thr,
// 16 warps (4x4), warp tile 32x64. 4-stage cp.async pipeline.
// ===========================================================================
#define GBM 128
#define GBN 256
#define KCH 64
#define NCHUNK (D_DIM / KCH)                 // 8
#define TILE_A 16384                         // 128x64 fp16
#define TILE_BT 32768                        // 256x64 fp16
#define STAGE_B (TILE_A + TILE_BT)           // 48KB
#define NSTAGE 4
#define SMEM_TOTAL (NSTAGE * STAGE_B)        // 196608

__global__ void __launch_bounds__(512, 1) gemm_mma(
    float* __restrict__ Cmat, int Ccls)
{
    extern __shared__ char smem[];
    const uint32_t sbase = smem_u32(smem);

    const int tid = threadIdx.x;
    const int wid = tid >> 5, l = tid & 31;
    const int wy = wid >> 2, wx = wid & 3;          // 4x4 warps, 32x64 tiles
    const int bm = blockIdx.y * GBM, bn = blockIdx.x * GBN;

    // ---- cp.async fill mapping: q = 16B segment, r0 = base row ----
    const int q = tid & 7;
    const int r0 = tid >> 3;          // 0..63
    uint32_t dA[2], dB[4];
    const char *srcA[2], *srcB[4];
    #pragma unroll
    for (int s = 0; s < 2; s++) {
        dA[s]   = sw128((uint32_t)((r0 + 64 * s) * 128 + q * 16));
        srcA[s] = reinterpret_cast<const char*>(g_Ah)
                + ((size_t)(bm + r0 + 64 * s) * D_DIM + q * 8) * 2;
    }
    #pragma unroll
    for (int s = 0; s < 4; s++) {
        dB[s]   = sw128((uint32_t)((r0 + 64 * s) * 128 + q * 16));
        srcB[s] = reinterpret_cast<const char*>(g_Bh)
                + ((size_t)(bn + r0 + 64 * s) * D_DIM + q * 8) * 2;
    }

    auto issue_stage = [&](int c) {
        const uint32_t st = sbase + (uint32_t)(c % NSTAGE) * STAGE_B;
        const int koff = c * KCH * 2;
        #pragma unroll
        for (int s = 0; s < 2; s++) cp16(st + dA[s], srcA[s] + koff);
        #pragma unroll
        for (int s = 0; s < 4; s++) cp16(st + TILE_A + dB[s], srcB[s] + koff);
        cp_commit();
    };

    // ---- ldmatrix lane addressing (validated R5-R7) ----
    const int a_row = (l & 15);
    const int a_kh  = (l >> 4);
    const int b_row = (l & 7) + (l >> 4) * 8;
    const int b_kh  = (l >> 3) & 1;

    float acc[2][8][4];
    #pragma unroll
    for (int m = 0; m < 2; m++)
        #pragma unroll
        for (int n = 0; n < 8; n++)
            #pragma unroll
            for (int i = 0; i < 4; i++) acc[m][n][i] = 0.0f;

    issue_stage(0);
    issue_stage(1);
    issue_stage(2);

    for (int c = 0; c < NCHUNK; c++) {
        cp_wait<2>();
        __syncthreads();
        if (c + 3 < NCHUNK) issue_stage(c + 3);

        const uint32_t ah_b = sbase + (uint32_t)(c % NSTAGE) * STAGE_B;
        const uint32_t bh_b = ah_b + TILE_A;

        #pragma unroll
        for (int ks = 0; ks < 4; ks++) {
            uint32_t ah[2][4], bh[4][4];
            #pragma unroll
            for (int mb = 0; mb < 2; mb++) {
                const uint32_t off = sw128((uint32_t)(
                    (wy * 32 + mb * 16 + a_row) * 128 + ks * 32 + a_kh * 16));
                ldsm_x4(ah[mb][0], ah[mb][1], ah[mb][2], ah[mb][3], ah_b + off);
            }
            #pragma unroll
            for (int nb2 = 0; nb2 < 4; nb2++) {
                const uint32_t off = sw128((uint32_t)(
                    (wx * 64 + nb2 * 16 + b_row) * 128 + ks * 32 + b_kh * 16));
                ldsm_x4(bh[nb2][0], bh[nb2][1], bh[nb2][2], bh[nb2][3], bh_b + off);
            }
            #pragma unroll
            for (int mb = 0; mb < 2; mb++)
                #pragma unroll
                for (int nb2 = 0; nb2 < 4; nb2++)
                    #pragma unroll
                    for (int h = 0; h < 2; h++)
                        mma_f16(acc[mb][nb2 * 2 + h], ah[mb],
                                bh[nb2][h * 2], bh[nb2][h * 2 + 1]);
        }
    }

    // ---- epilogue ----
    #pragma unroll
    for (int mb = 0; mb < 2; mb++) {
        const int row = bm + wy * 32 + mb * 16 + (l >> 2);
        #pragma unroll
        for (int nb = 0; nb < 8; nb++) {
            const int col = bn + wx * 64 + nb * 8 + (l & 3) * 2;
            float* o0 = Cmat + (size_t)row * Ccls + col;
            float* o1 = o0 + (size_t)8 * Ccls;
            *reinterpret_cast<float2*>(o0) = make_float2(acc[mb][nb][0], acc[mb][nb][1]);
            *reinterpret_cast<float2*>(o1) = make_float2(acc[mb][nb][2], acc[mb][nb][3]);
        }
    }
}

// ---------------------------------------------------------------------------
extern "C" void kernel_launch(void* const* d_in, const int* in_sizes, int n_in,
                              void* d_out, int out_size)
{
    int i_feats = 0, i_protos = 0, i_labels = 0;
    for (int i = 1; i < n_in; i++) {
        if (in_sizes[i] > in_sizes[i_feats])  i_feats  = i;
        if (in_sizes[i] < in_sizes[i_labels]) i_labels = i;
    }
    for (int i = 0; i < n_in; i++)
        if (i != i_feats && i != i_labels) i_protos = i;

    const float* feats  = (const float*)d_in[i_feats];
    const float* protos = (const float*)d_in[i_protos];
    const void*  labels = d_in[i_labels];

    const int N = in_sizes[i_labels];
    const int C = in_sizes[i_protos] / D_DIM;
    float* out = (float*)d_out;

    {
        int total = MAX_C * D_DIM;
        zero_detect<<<(total + 255) / 256, 256>>>((const int*)labels, N);
    }
    normalize_scatter<<<N, 128>>>(feats, labels, C);
    proto_update<<<C, 128>>>(protos);

    static bool smem_set = false;
    if (!smem_set) {
        cudaFuncSetAttribute(gemm_mma, cudaFuncAttributeMaxDynamicSharedMemorySize,
                             SMEM_TOTAL);
        smem_set = true;
    }
    dim3 grid(C / GBN, N / GBM);   // (4, 512) = 2048 CTAs
    gemm_mma<<<grid, 512, SMEM_TOTAL>>>(out, C);
}